// round 4
// baseline (speedup 1.0000x reference)
#include <cuda_runtime.h>
#include <cstdint>
#include <cstddef>

#define BB 8
#define NN 4096
#define MM 1024
#define DD 64
#define PTS 16
#define NPAIR 8
#define FPS_THREADS 256   /* NN / PTS */
#define NWARP 8
#define OUT_COLS 134      /* D + 3 + D + 3 */
#define COPY_BLOCKS 64
#define TAIL_BLOCKS 8
#define ROWS_PER_COPY ((BB * NN) / COPY_BLOCKS)  /* 512 */
#define NCELL 512         /* 8x8x8 spatial grid */

// ---------------- scratch (no allocations allowed) ----------------
__device__ int   g_sidx[BB * MM];   // global index of sampled points
__device__ float g_lrx[BB * MM];    // sampled positions, SoA
__device__ float g_lry[BB * MM];
__device__ float g_lrz[BB * MM];

// ---------------- packed f32x2 helpers (bit-exact per-lane .rn ops) ------
__device__ __forceinline__ unsigned long long packf2(float lo, float hi) {
    unsigned long long r;
    asm("mov.b64 %0, {%1, %2};" : "=l"(r) : "f"(lo), "f"(hi));
    return r;
}
__device__ __forceinline__ void unpackf2(unsigned long long v, float& lo, float& hi) {
    asm("mov.b64 {%0, %1}, %2;" : "=f"(lo), "=f"(hi) : "l"(v));
}
__device__ __forceinline__ unsigned long long addx2(unsigned long long a, unsigned long long b) {
    unsigned long long r;
    asm("add.rn.f32x2 %0, %1, %2;" : "=l"(r) : "l"(a), "l"(b));
    return r;
}
__device__ __forceinline__ unsigned long long mulx2(unsigned long long a, unsigned long long b) {
    unsigned long long r;
    asm("mul.rn.f32x2 %0, %1, %2;" : "=l"(r) : "l"(a), "l"(b));
    return r;
}
__device__ __forceinline__ unsigned redux_max_u32(unsigned v) {
    unsigned r;
    asm("redux.sync.max.u32 %0, %1, 0xffffffff;" : "=r"(r) : "r"(v));
    return r;
}

struct FpsShared {
    unsigned long long wkey[2][NWARP];            // double-buffered per-warp keys
    unsigned long long xs2[NN], ys2[NN], zs2[NN]; // sorted coords duplicated (v,v)
    unsigned orig[NN];                            // sorted slot -> original local idx
    unsigned cnt[NCELL], offs[NCELL];
    int pos0;                                     // sorted slot of original point 0
};

// ---------------- Kernel 1: FPS (blocks 0..7) + overlapped copy/zero/batch ------------
__global__ __launch_bounds__(FPS_THREADS, 1)
void fps_kernel(const float* __restrict__ x, const float* __restrict__ pos,
                float* __restrict__ out, long long out_size) {
    if (blockIdx.x >= BB) {
        const int cb = blockIdx.x - BB;
        if (cb < COPY_BLOCKS) {
            // out[:, 0:67] = [x | pos]  (independent of FPS -> runs concurrently)
            const int r0 = cb * ROWS_PER_COPY;
            for (int e = threadIdx.x; e < ROWS_PER_COPY * 67; e += FPS_THREADS) {
                int r = r0 + e / 67;
                int c = e - 67 * (e / 67);
                float v = (c < DD) ? x[(size_t)r * DD + c] : pos[3 * r + (c - DD)];
                out[(size_t)r * OUT_COLS + c] = v;
            }
        } else {
            const long long outx = (long long)BB * NN * OUT_COLS;
            const long long zs = (long long)BB * NN * 3;
            const int gt = (cb - COPY_BLOCKS) * FPS_THREADS + threadIdx.x;
            if (out_size >= outx + zs)
                for (long long i = gt; i < zs; i += (long long)TAIL_BLOCKS * FPS_THREADS)
                    out[outx + i] = 0.0f;
            if (out_size >= outx + zs + (long long)BB * NN)
                for (int i = gt; i < BB * NN; i += TAIL_BLOCKS * FPS_THREADS)
                    out[outx + zs + i] = (float)(i >> 12);  // i / NN
        }
        return;
    }

    extern __shared__ unsigned char smraw[];
    FpsShared* sm = reinterpret_cast<FpsShared*>(smraw);
    const int b = blockIdx.x;
    const int t = threadIdx.x;
    const int warp = t >> 5;
    const int lane = t & 31;
    const float* posb = pos + (size_t)b * NN * 3;

    // ---- counting sort into 8x8x8 cells (spatial locality for pruning) ----
    for (int i = t; i < NCELL; i += FPS_THREADS) sm->cnt[i] = 0u;
    __syncthreads();
#pragma unroll
    for (int j = 0; j < PTS; j++) {
        int i = t + j * FPS_THREADS;
        float X = posb[3 * i + 0], Y = posb[3 * i + 1], Z = posb[3 * i + 2];
        int ix = min(7, max(0, (int)(X * 8.0f)));
        int iy = min(7, max(0, (int)(Y * 8.0f)));
        int iz = min(7, max(0, (int)(Z * 8.0f)));
        atomicAdd(&sm->cnt[(ix << 6) | (iy << 3) | iz], 1u);
    }
    __syncthreads();
    if (t < 32) {  // exclusive scan of 512 counts, warp 0
        unsigned loc[16], run = 0;
        int cb0 = t * 16;
#pragma unroll
        for (int c = 0; c < 16; c++) { loc[c] = run; run += sm->cnt[cb0 + c]; }
        unsigned excl = run;
#pragma unroll
        for (int o = 1; o < 32; o <<= 1) {
            unsigned v = __shfl_up_sync(0xFFFFFFFFu, excl, o);
            if (lane >= o) excl += v;
        }
        excl -= run;  // exclusive
#pragma unroll
        for (int c = 0; c < 16; c++) sm->offs[cb0 + c] = excl + loc[c];
    }
    __syncthreads();
#pragma unroll
    for (int j = 0; j < PTS; j++) {
        int i = t + j * FPS_THREADS;
        float X = posb[3 * i + 0], Y = posb[3 * i + 1], Z = posb[3 * i + 2];
        int ix = min(7, max(0, (int)(X * 8.0f)));
        int iy = min(7, max(0, (int)(Y * 8.0f)));
        int iz = min(7, max(0, (int)(Z * 8.0f)));
        unsigned p = atomicAdd(&sm->offs[(ix << 6) | (iy << 3) | iz], 1u);
        sm->xs2[p] = packf2(X, X);
        sm->ys2[p] = packf2(Y, Y);
        sm->zs2[p] = packf2(Z, Z);
        sm->orig[p] = (unsigned)i;
        if (i == 0) sm->pos0 = (int)p;
    }
    __syncthreads();

    // ---- per-thread registers: 16 sorted points (compact bbox) ----
    const int base = t * PTS;
    unsigned long long npx[NPAIR], npy[NPAIR], npz[NPAIR];
    float mind[PTS];
    float bxmin = 3.4e38f, bxmax = -3.4e38f, bymin = 3.4e38f, bymax = -3.4e38f,
          bzmin = 3.4e38f, bzmax = -3.4e38f;
#pragma unroll
    for (int p = 0; p < NPAIR; p++) {
        float a0, a1, dum;
        unpackf2(sm->xs2[base + 2 * p], a0, dum);
        unpackf2(sm->xs2[base + 2 * p + 1], a1, dum);
        npx[p] = packf2(-a0, -a1);
        bxmin = fminf(bxmin, fminf(a0, a1)); bxmax = fmaxf(bxmax, fmaxf(a0, a1));
        unpackf2(sm->ys2[base + 2 * p], a0, dum);
        unpackf2(sm->ys2[base + 2 * p + 1], a1, dum);
        npy[p] = packf2(-a0, -a1);
        bymin = fminf(bymin, fminf(a0, a1)); bymax = fmaxf(bymax, fmaxf(a0, a1));
        unpackf2(sm->zs2[base + 2 * p], a0, dum);
        unpackf2(sm->zs2[base + 2 * p + 1], a1, dum);
        npz[p] = packf2(-a0, -a1);
        bzmin = fminf(bzmin, fminf(a0, a1)); bzmax = fmaxf(bzmax, fmaxf(a0, a1));
    }
#pragma unroll
    for (int j = 0; j < PTS; j++) mind[j] = 3.402823466e+38f;

    const int p0 = sm->pos0;
    unsigned long long lxx = sm->xs2[p0], lyy = sm->ys2[p0], lzz = sm->zs2[p0];
    float cx, cy, cz, dumf;
    unpackf2(lxx, cx, dumf); unpackf2(lyy, cy, dumf); unpackf2(lzz, cz, dumf);
    if (t == 0) {
        g_sidx[b * MM] = b * NN;
        g_lrx[b * MM] = cx; g_lry[b * MM] = cy; g_lrz[b * MM] = cz;
    }

    unsigned vb = __float_as_uint(3.402823466e+38f);  // thread's current max mind (bits)
    unsigned low = 0;                                  // (4095-orig)<<12 | sorted

    for (int step = 1; step < MM; ++step) {
        // bbox lower bound on distance^2 from current center
        float ddx = fmaxf(fmaxf(bxmin - cx, cx - bxmax), 0.0f);
        float ddy = fmaxf(fmaxf(bymin - cy, cy - bymax), 0.0f);
        float ddz = fmaxf(fmaxf(bzmin - cz, cz - bzmax), 0.0f);
        float lb2 = ddx * ddx + ddy * ddy + ddz * ddz;
        bool active = !(lb2 >= __uint_as_float(vb) * 1.00001f);

        if (active) {
#pragma unroll
            for (int p = 0; p < NPAIR; p++) {
                unsigned long long dx = addx2(lxx, npx[p]);
                unsigned long long dy = addx2(lyy, npy[p]);
                unsigned long long dz = addx2(lzz, npz[p]);
                unsigned long long s  = addx2(addx2(mulx2(dx, dx), mulx2(dy, dy)),
                                              mulx2(dz, dz));
                float d0, d1;
                unpackf2(s, d0, d1);
                mind[2 * p]     = fminf(mind[2 * p], d0);
                mind[2 * p + 1] = fminf(mind[2 * p + 1], d1);
            }
            // in-thread argmax tree, lower slot wins ties
            float v[NPAIR]; int id[NPAIR];
#pragma unroll
            for (int k = 0; k < NPAIR; k++) {
                bool keep = mind[2 * k] >= mind[2 * k + 1];
                v[k]  = keep ? mind[2 * k] : mind[2 * k + 1];
                id[k] = keep ? (2 * k) : (2 * k + 1);
            }
#pragma unroll
            for (int s = 1; s < NPAIR; s <<= 1) {
#pragma unroll
                for (int j = 0; j < NPAIR; j += 2 * s) {
                    bool keep = v[j] >= v[j + s];
                    v[j]  = keep ? v[j]  : v[j + s];
                    id[j] = keep ? id[j] : id[j + s];
                }
            }
            int swin = base + id[0];
            unsigned ow = sm->orig[swin];
            vb = __float_as_uint(v[0]);
            low = ((4095u - ow) << 12) | (unsigned)swin;
        }

        // warp argmax: max value bits, then max low (= min orig idx) among maxima
        unsigned vmax = redux_max_u32(vb);
        unsigned cand = (vb == vmax) ? low : 0u;
        unsigned lmax = redux_max_u32(cand);
        if (lane == 0)
            sm->wkey[step & 1][warp] =
                ((unsigned long long)vmax << 32) | (unsigned long long)lmax;
        __syncthreads();

        // cross-warp: every thread reduces the 8 keys serially (validated fastest)
        const unsigned long long* wk = sm->wkey[step & 1];
        unsigned long long bk = wk[0];
#pragma unroll
        for (int w = 1; w < NWARP; w++) {
            unsigned long long k = wk[w];
            if (k > bk) bk = k;
        }
        unsigned glow = (unsigned)bk;
        unsigned widx = glow & 4095u;
        lxx = sm->xs2[widx]; lyy = sm->ys2[widx]; lzz = sm->zs2[widx];
        unpackf2(lxx, cx, dumf); unpackf2(lyy, cy, dumf); unpackf2(lzz, cz, dumf);

        if (t == 0) {
            unsigned ow = 4095u - (glow >> 12);
            g_sidx[b * MM + step] = b * NN + (int)ow;
            g_lrx[b * MM + step] = cx;
            g_lry[b * MM + step] = cy;
            g_lrz[b * MM + step] = cz;
        }
    }
}

// ---------------- Kernel 2: 1-NN (4 threads/row) + gather of cols 67..133 ----------
#define KROWS 64
__global__ __launch_bounds__(256)
void knn_out_kernel(const float* __restrict__ x, const float* __restrict__ pos,
                    float* __restrict__ out) {
    __shared__ unsigned long long nlx[MM / 2], nly[MM / 2], nlz[MM / 2];
    __shared__ int gsrc[KROWS];

    const int b = blockIdx.y;
    const float2* fx = (const float2*)(g_lrx) + b * (MM / 2);
    const float2* fy = (const float2*)(g_lry) + b * (MM / 2);
    const float2* fz = (const float2*)(g_lrz) + b * (MM / 2);
    for (int i = threadIdx.x; i < MM / 2; i += 256) {
        float2 a = fx[i]; nlx[i] = packf2(-a.x, -a.y);
        float2 c = fy[i]; nly[i] = packf2(-c.x, -c.y);
        float2 e = fz[i]; nlz[i] = packf2(-e.x, -e.y);
    }
    __syncthreads();

    const int r = threadIdx.x >> 2;          // row within block (0..63)
    const int q = threadIdx.x & 3;           // quarter of M
    const int rlocal = blockIdx.x * KROWS + r;
    const int row = b * NN + rlocal;
    const float ax = pos[3 * row + 0];
    const float ay = pos[3 * row + 1];
    const float az = pos[3 * row + 2];
    const unsigned long long axx = packf2(ax, ax);
    const unsigned long long ayy = packf2(ay, ay);
    const unsigned long long azz = packf2(az, az);

    const int j0 = q * (MM / 4);
    float bv0 = 3.4e+38f, bv1 = 3.4e+38f, bv2 = 3.4e+38f, bv3 = 3.4e+38f;
    int bi0 = j0, bi1 = j0 + 1, bi2 = j0 + 2, bi3 = j0 + 3;
    for (int j = j0; j < j0 + MM / 4; j += 4) {
        int p = j >> 1;
        unsigned long long dxA = addx2(axx, nlx[p]);
        unsigned long long dyA = addx2(ayy, nly[p]);
        unsigned long long dzA = addx2(azz, nlz[p]);
        unsigned long long sA  = addx2(addx2(mulx2(dxA, dxA), mulx2(dyA, dyA)),
                                       mulx2(dzA, dzA));
        unsigned long long dxB = addx2(axx, nlx[p + 1]);
        unsigned long long dyB = addx2(ayy, nly[p + 1]);
        unsigned long long dzB = addx2(azz, nlz[p + 1]);
        unsigned long long sB  = addx2(addx2(mulx2(dxB, dxB), mulx2(dyB, dyB)),
                                       mulx2(dzB, dzB));
        float d0, d1, d2, d3;
        unpackf2(sA, d0, d1);
        unpackf2(sB, d2, d3);
        if (d0 < bv0) { bv0 = d0; bi0 = j + 0; }
        if (d1 < bv1) { bv1 = d1; bi1 = j + 1; }
        if (d2 < bv2) { bv2 = d2; bi2 = j + 2; }
        if (d3 < bv3) { bv3 = d3; bi3 = j + 3; }
    }
    bool t1 = (bv1 < bv0) || (bv1 == bv0 && bi1 < bi0);
    float va = t1 ? bv1 : bv0;  int ia = t1 ? bi1 : bi0;
    bool t2 = (bv3 < bv2) || (bv3 == bv2 && bi3 < bi2);
    float vx = t2 ? bv3 : bv2;  int ib = t2 ? bi3 : bi2;
    bool t3 = (vx < va) || (vx == va && ib < ia);
    float bv = t3 ? vx : va;  int bi = t3 ? ib : ia;

    // combine 4 partials across lanes q=0..3 (first-index tie-break)
#pragma unroll
    for (int o = 1; o < 4; o <<= 1) {
        float ov = __shfl_xor_sync(0xFFFFFFFFu, bv, o);
        int   oi = __shfl_xor_sync(0xFFFFFFFFu, bi, o);
        if ((ov < bv) || (ov == bv && oi < bi)) { bv = ov; bi = oi; }
    }
    if (q == 0) gsrc[r] = g_sidx[b * MM + bi];
    __syncthreads();

    // Write cols 67..133: [x[g] | pos[g]] per row, cooperative + coalesced.
    const long long rowbase = (long long)b * NN + (long long)blockIdx.x * KROWS;
    for (int e = threadIdx.x; e < KROWS * 67; e += 256) {
        int rr = e / 67;
        int c = e - 67 * rr;
        int g = gsrc[rr];
        float val = (c < DD) ? x[(size_t)g * DD + c] : pos[3 * g + (c - DD)];
        out[((size_t)rowbase + rr) * OUT_COLS + 67 + c] = val;
    }
}

extern "C" void kernel_launch(void* const* d_in, const int* in_sizes, int n_in,
                              void* d_out, int out_size) {
    const float* x   = (const float*)d_in[0];
    const float* pos = (const float*)d_in[1];
    float* out = (float*)d_out;

    cudaFuncSetAttribute(fps_kernel, cudaFuncAttributeMaxDynamicSharedMemorySize,
                         (int)sizeof(FpsShared));
    fps_kernel<<<BB + COPY_BLOCKS + TAIL_BLOCKS, FPS_THREADS, sizeof(FpsShared)>>>(
        x, pos, out, (long long)out_size);
    knn_out_kernel<<<dim3(NN / KROWS, BB), 256>>>(x, pos, out);
}

// round 5
// speedup vs baseline: 1.1371x; 1.1371x over previous
#include <cuda_runtime.h>
#include <cstdint>
#include <cstddef>

#define BB 8
#define NN 4096
#define MM 1024
#define DD 64
#define PTS 8
#define NPAIR 4
#define FPS_THREADS 512   /* NN / PTS */
#define NWARP 16
#define P2T 256
#define OUT_COLS 134      /* D + 3 + D + 3 */
#define COPY_BLOCKS 64
#define TAIL_BLOCKS 8
#define ROWS_PER_COPY ((BB * NN) / COPY_BLOCKS)  /* 512 */
#define NCELL 512         /* 8x8x8 spatial grid */

// ---------------- scratch (no allocations allowed) ----------------
__device__ int   g_sidx[BB * MM];
__device__ float g_lrx[BB * MM];
__device__ float g_lry[BB * MM];
__device__ float g_lrz[BB * MM];

// ---------------- packed f32x2 helpers (bit-exact per-lane .rn ops) ------
__device__ __forceinline__ unsigned long long packf2(float lo, float hi) {
    unsigned long long r;
    asm("mov.b64 %0, {%1, %2};" : "=l"(r) : "f"(lo), "f"(hi));
    return r;
}
__device__ __forceinline__ void unpackf2(unsigned long long v, float& lo, float& hi) {
    asm("mov.b64 {%0, %1}, %2;" : "=f"(lo), "=f"(hi) : "l"(v));
}
__device__ __forceinline__ unsigned long long addx2(unsigned long long a, unsigned long long b) {
    unsigned long long r;
    asm("add.rn.f32x2 %0, %1, %2;" : "=l"(r) : "l"(a), "l"(b));
    return r;
}
__device__ __forceinline__ unsigned long long mulx2(unsigned long long a, unsigned long long b) {
    unsigned long long r;
    asm("mul.rn.f32x2 %0, %1, %2;" : "=l"(r) : "l"(a), "l"(b));
    return r;
}
__device__ __forceinline__ unsigned redux_max_u32(unsigned v) {
    unsigned r;
    asm("redux.sync.max.u32 %0, %1, 0xffffffff;" : "=r"(r) : "r"(v));
    return r;
}

struct FpsShared {
    unsigned long long wkey[2][NWARP];            // double-buffered per-warp keys
    unsigned long long xs2[NN], ys2[NN], zs2[NN]; // sorted coords duplicated (v,v)
    unsigned orig[NN];                            // sorted slot -> original local idx
    unsigned cnt[NCELL], offs[NCELL];
    int pos0;
};

// ---------------- Kernel 1: FPS (blocks 0..7) + overlapped copy/zero/batch ------------
__global__ __launch_bounds__(FPS_THREADS, 1)
void fps_kernel(const float* __restrict__ x, const float* __restrict__ pos,
                float* __restrict__ out, long long out_size) {
    if (blockIdx.x >= BB) {
        const int cb = blockIdx.x - BB;
        if (cb < COPY_BLOCKS) {
            const int r0 = cb * ROWS_PER_COPY;
            for (int e = threadIdx.x; e < ROWS_PER_COPY * 67; e += FPS_THREADS) {
                int r = r0 + e / 67;
                int c = e - 67 * (e / 67);
                float v = (c < DD) ? x[(size_t)r * DD + c] : pos[3 * r + (c - DD)];
                out[(size_t)r * OUT_COLS + c] = v;
            }
        } else {
            const long long outx = (long long)BB * NN * OUT_COLS;
            const long long zs = (long long)BB * NN * 3;
            const int gt = (cb - COPY_BLOCKS) * FPS_THREADS + threadIdx.x;
            if (out_size >= outx + zs)
                for (long long i = gt; i < zs; i += (long long)TAIL_BLOCKS * FPS_THREADS)
                    out[outx + i] = 0.0f;
            if (out_size >= outx + zs + (long long)BB * NN)
                for (int i = gt; i < BB * NN; i += TAIL_BLOCKS * FPS_THREADS)
                    out[outx + zs + i] = (float)(i >> 12);
        }
        return;
    }

    extern __shared__ unsigned char smraw[];
    FpsShared* sm = reinterpret_cast<FpsShared*>(smraw);
    const int b = blockIdx.x;
    const int t = threadIdx.x;
    const int warp = t >> 5;
    const int lane = t & 31;
    const float* posb = pos + (size_t)b * NN * 3;

    // ---- counting sort into 8x8x8 cells ----
    for (int i = t; i < NCELL; i += FPS_THREADS) sm->cnt[i] = 0u;
    __syncthreads();
#pragma unroll
    for (int j = 0; j < PTS; j++) {
        int i = t + j * FPS_THREADS;
        float X = posb[3 * i + 0], Y = posb[3 * i + 1], Z = posb[3 * i + 2];
        int ix = min(7, max(0, (int)(X * 8.0f)));
        int iy = min(7, max(0, (int)(Y * 8.0f)));
        int iz = min(7, max(0, (int)(Z * 8.0f)));
        atomicAdd(&sm->cnt[(ix << 6) | (iy << 3) | iz], 1u);
    }
    __syncthreads();
    if (t < 32) {  // exclusive scan of 512 counts in warp 0
        unsigned loc[16], run = 0;
        int cb0 = t * 16;
#pragma unroll
        for (int c = 0; c < 16; c++) { loc[c] = run; run += sm->cnt[cb0 + c]; }
        unsigned excl = run;
#pragma unroll
        for (int o = 1; o < 32; o <<= 1) {
            unsigned v = __shfl_up_sync(0xFFFFFFFFu, excl, o);
            if (lane >= o) excl += v;
        }
        excl -= run;
#pragma unroll
        for (int c = 0; c < 16; c++) sm->offs[cb0 + c] = excl + loc[c];
    }
    __syncthreads();
#pragma unroll
    for (int j = 0; j < PTS; j++) {
        int i = t + j * FPS_THREADS;
        float X = posb[3 * i + 0], Y = posb[3 * i + 1], Z = posb[3 * i + 2];
        int ix = min(7, max(0, (int)(X * 8.0f)));
        int iy = min(7, max(0, (int)(Y * 8.0f)));
        int iz = min(7, max(0, (int)(Z * 8.0f)));
        unsigned p = atomicAdd(&sm->offs[(ix << 6) | (iy << 3) | iz], 1u);
        sm->xs2[p] = packf2(X, X);
        sm->ys2[p] = packf2(Y, Y);
        sm->zs2[p] = packf2(Z, Z);
        sm->orig[p] = (unsigned)i;
        if (i == 0) sm->pos0 = (int)p;
    }
    __syncthreads();

    // ---- per-thread registers: 8 sorted points (compact bbox) ----
    const int base = t * PTS;
    unsigned long long npx[NPAIR], npy[NPAIR], npz[NPAIR];
    float mind[PTS];
    float bxmin = 3.4e38f, bxmax = -3.4e38f, bymin = 3.4e38f, bymax = -3.4e38f,
          bzmin = 3.4e38f, bzmax = -3.4e38f;
#pragma unroll
    for (int p = 0; p < NPAIR; p++) {
        float a0, a1, dum;
        unpackf2(sm->xs2[base + 2 * p], a0, dum);
        unpackf2(sm->xs2[base + 2 * p + 1], a1, dum);
        npx[p] = packf2(-a0, -a1);
        bxmin = fminf(bxmin, fminf(a0, a1)); bxmax = fmaxf(bxmax, fmaxf(a0, a1));
        unpackf2(sm->ys2[base + 2 * p], a0, dum);
        unpackf2(sm->ys2[base + 2 * p + 1], a1, dum);
        npy[p] = packf2(-a0, -a1);
        bymin = fminf(bymin, fminf(a0, a1)); bymax = fmaxf(bymax, fmaxf(a0, a1));
        unpackf2(sm->zs2[base + 2 * p], a0, dum);
        unpackf2(sm->zs2[base + 2 * p + 1], a1, dum);
        npz[p] = packf2(-a0, -a1);
        bzmin = fminf(bzmin, fminf(a0, a1)); bzmax = fmaxf(bzmax, fmaxf(a0, a1));
    }
#pragma unroll
    for (int j = 0; j < PTS; j++) mind[j] = 3.402823466e+38f;

    const int p0 = sm->pos0;
    unsigned long long lxx = sm->xs2[p0], lyy = sm->ys2[p0], lzz = sm->zs2[p0];
    float cx, cy, cz, dumf;
    unpackf2(lxx, cx, dumf); unpackf2(lyy, cy, dumf); unpackf2(lzz, cz, dumf);
    if (t == 0) {
        g_sidx[b * MM] = b * NN;
        g_lrx[b * MM] = cx; g_lry[b * MM] = cy; g_lrz[b * MM] = cz;
    }

    unsigned vb = __float_as_uint(3.402823466e+38f);  // thread max-mind bits
    unsigned low = 0;                                  // (4095-orig)<<12 | sorted

    for (int step = 1; step < MM; ++step) {
        // bbox lower bound on distance^2 from current center; skip is key-preserving.
        float ddx = fmaxf(fmaxf(bxmin - cx, cx - bxmax), 0.0f);
        float ddy = fmaxf(fmaxf(bymin - cy, cy - bymax), 0.0f);
        float ddz = fmaxf(fmaxf(bzmin - cz, cz - bzmax), 0.0f);
        float lb2 = ddx * ddx + ddy * ddy + ddz * ddz;
        bool active = !(lb2 >= __uint_as_float(vb) * 1.00001f);

        if (active) {
            bool changed = false;
#pragma unroll
            for (int p = 0; p < NPAIR; p++) {
                unsigned long long dx = addx2(lxx, npx[p]);
                unsigned long long dy = addx2(lyy, npy[p]);
                unsigned long long dz = addx2(lzz, npz[p]);
                unsigned long long s  = addx2(addx2(mulx2(dx, dx), mulx2(dy, dy)),
                                              mulx2(dz, dz));
                float d0, d1;
                unpackf2(s, d0, d1);
                changed |= (d0 < mind[2 * p]) | (d1 < mind[2 * p + 1]);
                mind[2 * p]     = fminf(mind[2 * p], d0);
                mind[2 * p + 1] = fminf(mind[2 * p + 1], d1);
            }
            if (changed) {  // recompute exact (vb, low); else stored key still exact
                float v[NPAIR]; int id[NPAIR];
#pragma unroll
                for (int k = 0; k < NPAIR; k++) {
                    bool keep = mind[2 * k] >= mind[2 * k + 1];
                    v[k]  = keep ? mind[2 * k] : mind[2 * k + 1];
                    id[k] = keep ? (2 * k) : (2 * k + 1);
                }
#pragma unroll
                for (int s = 1; s < NPAIR; s <<= 1) {
#pragma unroll
                    for (int j = 0; j < NPAIR; j += 2 * s) {
                        bool keep = v[j] >= v[j + s];
                        v[j]  = keep ? v[j]  : v[j + s];
                        id[j] = keep ? id[j] : id[j + s];
                    }
                }
                int swin = base + id[0];
                vb = __float_as_uint(v[0]);
                low = ((4095u - sm->orig[swin]) << 12) | (unsigned)swin;
            }
        }

        // warp argmax: max value bits, then max low (= min orig idx) among maxima
        unsigned vmax = redux_max_u32(vb);
        unsigned cand = (vb == vmax) ? low : 0u;
        unsigned lmax = redux_max_u32(cand);
        if (lane == 0)
            sm->wkey[step & 1][warp] =
                ((unsigned long long)vmax << 32) | (unsigned long long)lmax;
        __syncthreads();

        // cross-warp (16 keys): one key per lane, two redux.
        unsigned long long k = sm->wkey[step & 1][lane & (NWARP - 1)];
        unsigned hi = (unsigned)(k >> 32), lo = (unsigned)k;
        unsigned gv = redux_max_u32(hi);
        unsigned gc = (hi == gv) ? lo : 0u;
        unsigned gi = redux_max_u32(gc);
        unsigned widx = gi & 4095u;

        lxx = sm->xs2[widx]; lyy = sm->ys2[widx]; lzz = sm->zs2[widx];
        unpackf2(lxx, cx, dumf); unpackf2(lyy, cy, dumf); unpackf2(lzz, cz, dumf);

        if (t == 0) {
            g_sidx[b * MM + step] = b * NN + (int)(4095u - (gi >> 12));
            g_lrx[b * MM + step] = cx;
            g_lry[b * MM + step] = cy;
            g_lrz[b * MM + step] = cz;
        }
    }
}

// ---------------- Kernel 2: 1-NN (1 thread/row, broadcast LDS) + gather cols 67..133 ----
__global__ __launch_bounds__(P2T)
void knn_out_kernel(const float* __restrict__ x, const float* __restrict__ pos,
                    float* __restrict__ out) {
    __shared__ unsigned long long nlx[MM / 2], nly[MM / 2], nlz[MM / 2];
    __shared__ int gsrc[P2T];

    const int b = blockIdx.y;
    const float2* fx = (const float2*)(g_lrx) + b * (MM / 2);
    const float2* fy = (const float2*)(g_lry) + b * (MM / 2);
    const float2* fz = (const float2*)(g_lrz) + b * (MM / 2);
    for (int i = threadIdx.x; i < MM / 2; i += P2T) {
        float2 a = fx[i]; nlx[i] = packf2(-a.x, -a.y);
        float2 c = fy[i]; nly[i] = packf2(-c.x, -c.y);
        float2 e = fz[i]; nlz[i] = packf2(-e.x, -e.y);
    }
    __syncthreads();

    const int rlocal = blockIdx.x * P2T + threadIdx.x;
    const int row = b * NN + rlocal;
    const float ax = pos[3 * row + 0];
    const float ay = pos[3 * row + 1];
    const float az = pos[3 * row + 2];
    const unsigned long long axx = packf2(ax, ax);
    const unsigned long long ayy = packf2(ay, ay);
    const unsigned long long azz = packf2(az, az);

    float bv0 = 3.4e+38f, bv1 = 3.4e+38f, bv2 = 3.4e+38f, bv3 = 3.4e+38f;
    int bi0 = 0, bi1 = 1, bi2 = 2, bi3 = 3;
    for (int j = 0; j < MM; j += 4) {
        int p = j >> 1;
        unsigned long long dxA = addx2(axx, nlx[p]);
        unsigned long long dyA = addx2(ayy, nly[p]);
        unsigned long long dzA = addx2(azz, nlz[p]);
        unsigned long long sA  = addx2(addx2(mulx2(dxA, dxA), mulx2(dyA, dyA)),
                                       mulx2(dzA, dzA));
        unsigned long long dxB = addx2(axx, nlx[p + 1]);
        unsigned long long dyB = addx2(ayy, nly[p + 1]);
        unsigned long long dzB = addx2(azz, nlz[p + 1]);
        unsigned long long sB  = addx2(addx2(mulx2(dxB, dxB), mulx2(dyB, dyB)),
                                       mulx2(dzB, dzB));
        float d0, d1, d2, d3;
        unpackf2(sA, d0, d1);
        unpackf2(sB, d2, d3);
        if (d0 < bv0) { bv0 = d0; bi0 = j + 0; }
        if (d1 < bv1) { bv1 = d1; bi1 = j + 1; }
        if (d2 < bv2) { bv2 = d2; bi2 = j + 2; }
        if (d3 < bv3) { bv3 = d3; bi3 = j + 3; }
    }
    bool t1 = (bv1 < bv0) || (bv1 == bv0 && bi1 < bi0);
    float va = t1 ? bv1 : bv0;  int ia = t1 ? bi1 : bi0;
    bool t2 = (bv3 < bv2) || (bv3 == bv2 && bi3 < bi2);
    float vbv = t2 ? bv3 : bv2;  int ib = t2 ? bi3 : bi2;
    bool t3 = (vbv < va) || (vbv == va && ib < ia);
    int bi = t3 ? ib : ia;

    gsrc[threadIdx.x] = g_sidx[b * MM + bi];
    __syncthreads();

    const long long rowbase = (long long)b * NN + (long long)blockIdx.x * P2T;
    for (int e = threadIdx.x; e < P2T * 67; e += P2T) {
        int r = e / 67;
        int c = e - 67 * r;
        int g = gsrc[r];
        float val = (c < DD) ? x[(size_t)g * DD + c] : pos[3 * g + (c - DD)];
        out[((size_t)rowbase + r) * OUT_COLS + 67 + c] = val;
    }
}

extern "C" void kernel_launch(void* const* d_in, const int* in_sizes, int n_in,
                              void* d_out, int out_size) {
    const float* x   = (const float*)d_in[0];
    const float* pos = (const float*)d_in[1];
    float* out = (float*)d_out;

    cudaFuncSetAttribute(fps_kernel, cudaFuncAttributeMaxDynamicSharedMemorySize,
                         (int)sizeof(FpsShared));
    fps_kernel<<<BB + COPY_BLOCKS + TAIL_BLOCKS, FPS_THREADS, sizeof(FpsShared)>>>(
        x, pos, out, (long long)out_size);
    knn_out_kernel<<<dim3(NN / P2T, BB), P2T>>>(x, pos, out);
}